// round 2
// baseline (speedup 1.0000x reference)
#include <cuda_runtime.h>
#include <cuda_bf16.h>
#include <cstdint>

#define NB 64
#define NT 512
#define NI 128
#define NH 256
#define NR 20
#define NDA 50
#define NC 10
#define G4 1024

// ----------------------------- device scratch ------------------------------
__device__ float g_S [NB * NR * NT];        // [b][r][t] attention scores
__device__ float g_E [NB * NT * NR];        // [b][t][r] exp(S - max)
__device__ float g_M [(size_t)NB * NT * NI];     // [b][t][i]
__device__ float g_GX[(size_t)NB * NT * G4];     // [b][t][g]
__device__ float g_h [2][NH * 64];          // [buf][hd*64 + bb]
__device__ unsigned g_bar;

// ------------------------------ init ---------------------------------------
__global__ void k_init() {
    int t = blockIdx.x * blockDim.x + threadIdx.x;
    if (t < NH * 64) g_h[0][t] = 1.0f;
    if (t == 0) g_bar = 0u;
}

// ------------------------------ K1: scores ---------------------------------
// S[b,r,t] = (tanh(x[b,t,:]@W1[d,:] + b1)) @ W2[r,:] + b2
__global__ void k_scores(const float* __restrict__ x,
                         const float* __restrict__ W1, const float* __restrict__ b1,
                         const float* __restrict__ W2, const float* __restrict__ b2) {
    __shared__ float W1s[NDA][NI + 1];
    __shared__ float W2s[NR][NDA + 1];
    __shared__ float b1s[NDA];
    __shared__ float b2s[NR];
    __shared__ float xr[8][NI];
    __shared__ float ssm[8][NDA + 1];
    int tid = threadIdx.x;
    for (int idx = tid; idx < NDA * NI; idx += 256) W1s[idx / NI][idx % NI] = W1[idx];
    for (int idx = tid; idx < NR * NDA; idx += 256) W2s[idx / NDA][idx % NDA] = W2[idx];
    if (tid < NDA) b1s[tid] = b1[tid];
    if (tid < NR)  b2s[tid] = b2[tid];
    __syncthreads();

    int w = tid >> 5, lane = tid & 31;
    int bt = blockIdx.x * 8 + w;                  // < 32768
    const float* xp = x + (size_t)bt * NI;
    for (int i = lane; i < NI; i += 32) xr[w][i] = xp[i];
    __syncwarp();
    for (int d = lane; d < NDA; d += 32) {
        float acc = b1s[d];
        #pragma unroll 16
        for (int i = 0; i < NI; i++) acc = fmaf(xr[w][i], W1s[d][i], acc);
        ssm[w][d] = tanhf(acc);
    }
    __syncwarp();
    if (lane < NR) {
        float acc = b2s[lane];
        #pragma unroll
        for (int d = 0; d < NDA; d++) acc = fmaf(ssm[w][d], W2s[lane][d], acc);
        int b = bt >> 9, t = bt & 511;
        g_S[((size_t)b * NR + lane) * NT + t] = acc;
    }
}

// ------------------------------ K1b: max + exp ------------------------------
__global__ void k_maxexp() {
    int br = blockIdx.x;                 // b*NR + r
    int b = br / NR, r = br % NR;
    const float* row = g_S + (size_t)br * NT;
    int tid = threadIdx.x;               // 128 threads
    float v[4];
    float m = -1e30f;
    #pragma unroll
    for (int j = 0; j < 4; j++) { v[j] = row[tid + j * 128]; m = fmaxf(m, v[j]); }
    __shared__ float red[4];
    for (int o = 16; o; o >>= 1) m = fmaxf(m, __shfl_xor_sync(~0u, m, o));
    if ((tid & 31) == 0) red[tid >> 5] = m;
    __syncthreads();
    m = fmaxf(fmaxf(red[0], red[1]), fmaxf(red[2], red[3]));
    #pragma unroll
    for (int j = 0; j < 4; j++) {
        int t = tid + j * 128;
        g_E[((size_t)b * NT + t) * NR + r] = __expf(v[j] - m);
    }
}

// ------------------------------ K2: prefix scan -> M ------------------------
// One block per batch. 512 threads: i = tid&127, rq = tid>>7 owns r in [5rq,5rq+5)
__global__ void k_prefix(const float* __restrict__ x) {
    int b = blockIdx.x;
    int tid = threadIdx.x;
    int i = tid & 127, rq = tid >> 7;
    int r0 = rq * 5;
    __shared__ float Esm[NR], Dinv[NR], Dsm[NR];
    __shared__ float part[4][NI];
    if (tid < NR) Dsm[tid] = 0.0f;
    float N[5] = {0.f, 0.f, 0.f, 0.f, 0.f};
    const float* xb = x + (size_t)b * NT * NI;
    const float* Eb = g_E + (size_t)b * NT * NR;
    float* Mb = g_M + (size_t)b * NT * NI;
    __syncthreads();
    for (int t = 0; t < NT; t++) {
        if (tid < NR) {
            float e = Eb[(size_t)t * NR + tid];
            float d = Dsm[tid] + e;
            Dsm[tid] = d;
            Esm[tid] = e;
            Dinv[tid] = __fdividef(1.0f, d);
        }
        __syncthreads();
        float xv = xb[(size_t)t * NI + i];
        float acc = 0.0f;
        #pragma unroll
        for (int j = 0; j < 5; j++) {
            N[j] = fmaf(Esm[r0 + j], xv, N[j]);
            acc = fmaf(N[j], Dinv[r0 + j], acc);
        }
        part[rq][i] = acc;
        __syncthreads();
        if (rq == 0)
            Mb[(size_t)t * NI + i] = (part[0][i] + part[1][i] + part[2][i] + part[3][i]) * 0.05f;
    }
}

// ------------------------------ K3: gx = M @ W_ih + b -----------------------
// C[32768,1024] = A[32768,128] * B[128,1024]; tiles 64x64, K tiled by 64.
__global__ void k_gemm(const float* __restrict__ Wih, const float* __restrict__ bias) {
    __shared__ float As[64][68];       // [m][k] padded
    __shared__ float Bs[64 * 64];      // [k][n]
    int tid = threadIdx.x;
    int tn = tid & 15, tm = tid >> 4;
    int m0 = blockIdx.x * 64;
    int n0 = blockIdx.y * 64;
    float acc[4][4] = {};
    for (int kc = 0; kc < 2; kc++) {
        for (int idx = tid; idx < 64 * 16; idx += 256) {
            int row = idx >> 4, c4 = idx & 15;
            float4 va = *(const float4*)&g_M[(size_t)(m0 + row) * NI + kc * 64 + c4 * 4];
            *(float4*)&As[row][c4 * 4] = va;
            float4 vb = *(const float4*)&Wih[(size_t)(kc * 64 + row) * G4 + n0 + c4 * 4];
            *(float4*)&Bs[row * 64 + c4 * 4] = vb;
        }
        __syncthreads();
        #pragma unroll 4
        for (int kk = 0; kk < 64; kk++) {
            float4 bv = *(const float4*)&Bs[kk * 64 + tn * 4];
            #pragma unroll
            for (int j = 0; j < 4; j++) {
                float av = As[tm * 4 + j][kk];
                acc[j][0] = fmaf(av, bv.x, acc[j][0]);
                acc[j][1] = fmaf(av, bv.y, acc[j][1]);
                acc[j][2] = fmaf(av, bv.z, acc[j][2]);
                acc[j][3] = fmaf(av, bv.w, acc[j][3]);
            }
        }
        __syncthreads();
    }
    float4 bb4 = *(const float4*)&bias[n0 + tn * 4];
    #pragma unroll
    for (int j = 0; j < 4; j++) {
        float4 o;
        o.x = acc[j][0] + bb4.x; o.y = acc[j][1] + bb4.y;
        o.z = acc[j][2] + bb4.z; o.w = acc[j][3] + bb4.w;
        *(float4*)&g_GX[(size_t)(m0 + tm * 4 + j) * G4 + n0 + tn * 4] = o;
    }
}

// ------------------------------ K4: LSTM recurrence -------------------------
// 128 persistent blocks x 256 threads. Block bk owns h-dims {2bk, 2bk+1} => 8 gate cols.
// smem: hs[256][64] (h, [k][bb]) | Ws[256][8] | gsm[2][8][64] | csm[2][64]
#define LSTM_SMEM ((NH * 64 + NH * 8 + 2 * 8 * 64 + 2 * 64) * 4)

__device__ __forceinline__ float sigmoidf_(float v) {
    return 1.0f / (1.0f + __expf(-v));
}

__global__ void __launch_bounds__(256, 1) k_lstm(const float* __restrict__ Whh) {
    extern __shared__ float sm[];
    float* hs  = sm;                        // 16384
    float* Ws  = hs + NH * 64;              // 2048
    float* gsm = Ws + NH * 8;               // 1024
    float* csm = gsm + 2 * 8 * 64;          // 128

    int bk = blockIdx.x;
    int tid = threadIdx.x;
    int w = tid >> 5, lane = tid & 31;
    int q = w & 3, p = lane;                // col-pair q, batch-pair p
    int half = (w < 4) ? 0 : 1;

    // one-time: stage W_hh slice.  Ws[k*8 + hi*4 + g] = Whh[k*1024 + g*256 + 2bk+hi]
    for (int idx = tid; idx < NH * 8; idx += 256) {
        int k = idx >> 3, c = idx & 7, hi = c >> 2, g = c & 3;
        Ws[idx] = Whh[(size_t)k * G4 + g * NH + 2 * bk + hi];
    }
    if (tid < 128) csm[tid] = 1.0f;
    __syncthreads();

    int bbg = tid & 63, hig = (tid >> 6) & 1;   // gate-phase mapping (tid<128)

    for (int t = 0; t < NT; t++) {
        const float* hin = g_h[t & 1];
        float* hout = g_h[(t + 1) & 1];

        // prefetch gx for gate phase
        float pg[4];
        if (tid < 128) {
            size_t base = ((size_t)bbg * NT + t) * G4 + (2 * bk + hig);
            #pragma unroll
            for (int g = 0; g < 4; g++) pg[g] = g_GX[base + (size_t)g * NH];
        }

        // stage h first half (k 0..127), .cg to bypass stale L1
        float4 r1[8];
        #pragma unroll
        for (int j = 0; j < 8; j++)
            r1[j] = __ldcg((const float4*)(hin + tid * 4 + j * 1024));
        #pragma unroll
        for (int j = 0; j < 8; j++)
            *(float4*)(hs + tid * 4 + j * 1024) = r1[j];
        __syncthreads();

        // issue loads for second half (k 128..255) -- overlap with phase A
        float4 r2[8];
        #pragma unroll
        for (int j = 0; j < 8; j++)
            r2[j] = __ldcg((const float4*)(hin + 8192 + tid * 4 + j * 1024));

        float a00 = 0.f, a01 = 0.f, a10 = 0.f, a11 = 0.f;
        {
            int kb = half ? 64 : 0;        // phase A quarter
            #pragma unroll 16
            for (int k = kb; k < kb + 64; k++) {
                float2 hv = *(const float2*)&hs[k * 64 + 2 * p];
                float2 wv = *(const float2*)&Ws[k * 8 + 2 * q];
                a00 = fmaf(hv.x, wv.x, a00);
                a01 = fmaf(hv.y, wv.x, a01);
                a10 = fmaf(hv.x, wv.y, a10);
                a11 = fmaf(hv.y, wv.y, a11);
            }
        }
        #pragma unroll
        for (int j = 0; j < 8; j++)
            *(float4*)(hs + 8192 + tid * 4 + j * 1024) = r2[j];
        __syncthreads();
        {
            int kb = half ? 192 : 128;     // phase B quarter
            #pragma unroll 16
            for (int k = kb; k < kb + 64; k++) {
                float2 hv = *(const float2*)&hs[k * 64 + 2 * p];
                float2 wv = *(const float2*)&Ws[k * 8 + 2 * q];
                a00 = fmaf(hv.x, wv.x, a00);
                a01 = fmaf(hv.y, wv.x, a01);
                a10 = fmaf(hv.x, wv.y, a10);
                a11 = fmaf(hv.y, wv.y, a11);
            }
        }
        // gsm[half][col][bb]
        *(float2*)&gsm[half * 512 + (2 * q) * 64 + 2 * p]     = make_float2(a00, a01);
        *(float2*)&gsm[half * 512 + (2 * q + 1) * 64 + 2 * p] = make_float2(a10, a11);
        __syncthreads();

        if (tid < 128) {
            int ci = hig * 4;
            float di = gsm[ci * 64 + bbg]       + gsm[512 + ci * 64 + bbg];
            float df = gsm[(ci + 1) * 64 + bbg] + gsm[512 + (ci + 1) * 64 + bbg];
            float dg = gsm[(ci + 2) * 64 + bbg] + gsm[512 + (ci + 2) * 64 + bbg];
            float do_ = gsm[(ci + 3) * 64 + bbg] + gsm[512 + (ci + 3) * 64 + bbg];
            float i_t = sigmoidf_(pg[0] + di);
            float f_t = sigmoidf_(pg[1] + df);
            float g_t = tanhf(pg[2] + dg);
            float o_t = sigmoidf_(pg[3] + do_);
            float c = f_t * csm[tid] + i_t * g_t;
            csm[tid] = c;
            float hval = o_t * tanhf(c);
            __stcg(&hout[(2 * bk + hig) * 64 + bbg], hval);
        }
        __syncthreads();

        // grid barrier (counter, generation = 128*(t+1))
        if (tid == 0) {
            __threadfence();
            atomicAdd(&g_bar, 1u);
            unsigned target = 128u * (unsigned)(t + 1);
            while (*(volatile unsigned*)&g_bar < target) { }
        }
        __syncthreads();
    }
}

// ------------------------------ K5: head + softmax --------------------------
__global__ void k_head(const float* __restrict__ Wfc, const float* __restrict__ bfc,
                       float* __restrict__ out) {
    int b = blockIdx.x;
    int lane = threadIdx.x;    // 32
    __shared__ float hsm[NH];
    for (int k = lane; k < NH; k += 32) hsm[k] = g_h[0][k * 64 + b];
    __syncwarp();
    float l = -1e30f;
    if (lane < NC) {
        float acc = bfc[lane];
        #pragma unroll 8
        for (int k = 0; k < NH; k++) acc = fmaf(hsm[k], Wfc[lane * NH + k], acc);
        l = acc;
    }
    float m = l;
    for (int o = 16; o; o >>= 1) m = fmaxf(m, __shfl_xor_sync(~0u, m, o));
    float e = (lane < NC) ? __expf(l - m) : 0.0f;
    float s = e;
    for (int o = 16; o; o >>= 1) s += __shfl_xor_sync(~0u, s, o);
    if (lane < NC) out[b * NC + lane] = e / s;
}

// ------------------------------ launch --------------------------------------
extern "C" void kernel_launch(void* const* d_in, const int* in_sizes, int n_in,
                              void* d_out, int out_size) {
    const float* x    = (const float*)d_in[0];
    const float* W_ih = (const float*)d_in[1];
    const float* W_hh = (const float*)d_in[2];
    const float* b    = (const float*)d_in[3];
    const float* W1   = (const float*)d_in[4];
    const float* b1   = (const float*)d_in[5];
    const float* W2   = (const float*)d_in[6];
    const float* b2   = (const float*)d_in[7];
    const float* Wfc  = (const float*)d_in[8];
    const float* bfc  = (const float*)d_in[9];
    float* out = (float*)d_out;

    cudaFuncSetAttribute(k_lstm, cudaFuncAttributeMaxDynamicSharedMemorySize, LSTM_SMEM);

    k_init<<<64, 256>>>();
    k_scores<<<4096, 256>>>(x, W1, b1, W2, b2);
    k_maxexp<<<NB * NR, 128>>>();
    k_prefix<<<NB, 512>>>(x);
    {
        dim3 grid(512, 16);
        k_gemm<<<grid, 256>>>(W_ih, b);
    }
    k_lstm<<<128, 256, LSTM_SMEM>>>(W_hh);
    k_head<<<NB, 32>>>(Wfc, bfc, out);
}

// round 3
// speedup vs baseline: 1.0633x; 1.0633x over previous
#include <cuda_runtime.h>
#include <cuda_bf16.h>
#include <cstdint>

#define NB 64
#define NT 512
#define NI 128
#define NH 256
#define NR 20
#define NDA 50
#define NC 10
#define G4 1024

// ----------------------------- device scratch ------------------------------
__device__ float g_S [NB * NR * NT];             // [b][r][t]
__device__ float g_E [NB * NT * NR];             // [b][t][r]
__device__ float g_M [(size_t)NB * NT * NI];     // [b][t][i]
__device__ float g_GX [(size_t)NB * NT * G4];    // [b*t][g]   (gemm output)
__device__ float g_GXT[(size_t)NT * G4 * NB];    // [t][g][b]  (repacked)
__device__ float g_cE [NB * 8 * NR];             // chunk sums of E
__device__ float g_cN [NB * 8 * NR * NI];        // chunk sums of E*x
__device__ float g_h [2][NH * 64];               // [buf][hd*64 + bb]
__device__ unsigned g_bar;

__device__ __forceinline__ void ffma2(unsigned long long& acc,
                                      unsigned long long a,
                                      unsigned long long b) {
    asm("fma.rn.f32x2 %0, %1, %2, %0;" : "+l"(acc) : "l"(a), "l"(b));
}
__device__ __forceinline__ float sigmoidf_(float v) {
    return 1.0f / (1.0f + __expf(-v));
}

// ------------------------------ init ---------------------------------------
__global__ void k_init() {
    int t = blockIdx.x * blockDim.x + threadIdx.x;
    if (t < NH * 64) g_h[0][t] = 1.0f;
    if (t == 0) g_bar = 0u;
}

// ------------------------------ K1: scores ---------------------------------
__global__ void k_scores(const float* __restrict__ x,
                         const float* __restrict__ W1, const float* __restrict__ b1,
                         const float* __restrict__ W2, const float* __restrict__ b2) {
    __shared__ float W1s[NDA][NI + 1];
    __shared__ float W2s[NR][NDA + 1];
    __shared__ float b1s[NDA];
    __shared__ float b2s[NR];
    __shared__ float xr[8][NI];
    __shared__ float ssm[8][NDA + 1];
    int tid = threadIdx.x;
    for (int idx = tid; idx < NDA * NI; idx += 256) W1s[idx / NI][idx % NI] = W1[idx];
    for (int idx = tid; idx < NR * NDA; idx += 256) W2s[idx / NDA][idx % NDA] = W2[idx];
    if (tid < NDA) b1s[tid] = b1[tid];
    if (tid < NR)  b2s[tid] = b2[tid];
    __syncthreads();

    int w = tid >> 5, lane = tid & 31;
    int bt = blockIdx.x * 8 + w;
    const float* xp = x + (size_t)bt * NI;
    for (int i = lane; i < NI; i += 32) xr[w][i] = xp[i];
    __syncwarp();
    for (int d = lane; d < NDA; d += 32) {
        float acc = b1s[d];
        #pragma unroll 16
        for (int i = 0; i < NI; i++) acc = fmaf(xr[w][i], W1s[d][i], acc);
        ssm[w][d] = tanhf(acc);
    }
    __syncwarp();
    if (lane < NR) {
        float acc = b2s[lane];
        #pragma unroll
        for (int d = 0; d < NDA; d++) acc = fmaf(ssm[w][d], W2s[lane][d], acc);
        int b = bt >> 9, t = bt & 511;
        g_S[((size_t)b * NR + lane) * NT + t] = acc;
    }
}

// ------------------------------ K1b: max + exp ------------------------------
__global__ void k_maxexp() {
    int br = blockIdx.x;
    int b = br / NR, r = br % NR;
    const float* row = g_S + (size_t)br * NT;
    int tid = threadIdx.x;               // 128
    float v[4];
    float m = -1e30f;
    #pragma unroll
    for (int j = 0; j < 4; j++) { v[j] = row[tid + j * 128]; m = fmaxf(m, v[j]); }
    __shared__ float red[4];
    for (int o = 16; o; o >>= 1) m = fmaxf(m, __shfl_xor_sync(~0u, m, o));
    if ((tid & 31) == 0) red[tid >> 5] = m;
    __syncthreads();
    m = fmaxf(fmaxf(red[0], red[1]), fmaxf(red[2], red[3]));
    #pragma unroll
    for (int j = 0; j < 4; j++) {
        int t = tid + j * 128;
        g_E[((size_t)b * NT + t) * NR + r] = __expf(v[j] - m);
    }
}

// ---------------- K2a: per-chunk partial sums (b, chunk of 64 t) ------------
__global__ void k_chunksum(const float* __restrict__ x) {
    int bc = blockIdx.x;           // b*8 + c
    int b = bc >> 3, c = bc & 7;
    int tid = threadIdx.x;         // 256
    int i = tid & 127, rh = tid >> 7;   // rh in {0,1}, 10 r each
    int r0 = rh * 10;
    __shared__ float xr[NI];
    __shared__ float Esm[NR];
    float N[10];
    #pragma unroll
    for (int j = 0; j < 10; j++) N[j] = 0.0f;
    float sE = 0.0f;
    for (int tl = 0; tl < 64; tl++) {
        int t = c * 64 + tl;
        __syncthreads();
        if (tid < 128) xr[tid] = x[((size_t)b * NT + t) * NI + tid];
        else if (tid < 128 + NR) {
            float e = g_E[((size_t)b * NT + t) * NR + (tid - 128)];
            Esm[tid - 128] = e;
            sE += e;
        }
        __syncthreads();
        float xv = xr[i];
        #pragma unroll
        for (int j = 0; j < 10; j++) N[j] = fmaf(Esm[r0 + j], xv, N[j]);
    }
    #pragma unroll
    for (int j = 0; j < 10; j++)
        g_cN[((size_t)bc * NR + r0 + j) * NI + i] = N[j];
    if (tid >= 128 && tid < 128 + NR)
        g_cE[bc * NR + (tid - 128)] = sE;
}

// ---------------- K2b: per-chunk sequential scan -> M ------------------------
__global__ void k_prefix2(const float* __restrict__ x) {
    int bc = blockIdx.x;
    int b = bc >> 3, c = bc & 7;
    int tid = threadIdx.x;         // 512
    int i = tid & 127, rq = tid >> 7;   // 5 r each
    int r0 = rq * 5;
    __shared__ float Esm[NR], Dinv[NR], Dsm[NR];
    __shared__ float part[4][NI];
    if (tid < NR) {
        float s = 0.0f;
        for (int cp = 0; cp < c; cp++) s += g_cE[(b * 8 + cp) * NR + tid];
        Dsm[tid] = s;
    }
    float N[5];
    #pragma unroll
    for (int j = 0; j < 5; j++) {
        float s = 0.0f;
        for (int cp = 0; cp < c; cp++)
            s += g_cN[((size_t)(b * 8 + cp) * NR + r0 + j) * NI + i];
        N[j] = s;
    }
    const float* xb = x + (size_t)b * NT * NI;
    const float* Eb = g_E + (size_t)b * NT * NR;
    float* Mb = g_M + (size_t)b * NT * NI;
    for (int tl = 0; tl < 64; tl++) {
        int t = c * 64 + tl;
        if (tid < NR) {
            float e = Eb[(size_t)t * NR + tid];
            float d = Dsm[tid] + e;
            Dsm[tid] = d;
            Esm[tid] = e;
            Dinv[tid] = __fdividef(1.0f, d);
        }
        __syncthreads();
        float xv = xb[(size_t)t * NI + i];
        float acc = 0.0f;
        #pragma unroll
        for (int j = 0; j < 5; j++) {
            N[j] = fmaf(Esm[r0 + j], xv, N[j]);
            acc = fmaf(N[j], Dinv[r0 + j], acc);
        }
        part[rq][i] = acc;
        __syncthreads();
        if (rq == 0)
            Mb[(size_t)t * NI + i] = (part[0][i] + part[1][i] + part[2][i] + part[3][i]) * 0.05f;
    }
}

// ------------------------------ K3: gx = M @ W_ih + b -----------------------
__global__ void k_gemm(const float* __restrict__ Wih, const float* __restrict__ bias) {
    __shared__ float As[64][68];
    __shared__ float Bs[64 * 64];
    int tid = threadIdx.x;
    int tn = tid & 15, tm = tid >> 4;
    int m0 = blockIdx.x * 64;
    int n0 = blockIdx.y * 64;
    float acc[4][4] = {};
    for (int kc = 0; kc < 2; kc++) {
        for (int idx = tid; idx < 64 * 16; idx += 256) {
            int row = idx >> 4, c4 = idx & 15;
            float4 va = *(const float4*)&g_M[(size_t)(m0 + row) * NI + kc * 64 + c4 * 4];
            *(float4*)&As[row][c4 * 4] = va;
            float4 vb = *(const float4*)&Wih[(size_t)(kc * 64 + row) * G4 + n0 + c4 * 4];
            *(float4*)&Bs[row * 64 + c4 * 4] = vb;
        }
        __syncthreads();
        #pragma unroll 4
        for (int kk = 0; kk < 64; kk++) {
            float4 bv = *(const float4*)&Bs[kk * 64 + tn * 4];
            #pragma unroll
            for (int j = 0; j < 4; j++) {
                float av = As[tm * 4 + j][kk];
                acc[j][0] = fmaf(av, bv.x, acc[j][0]);
                acc[j][1] = fmaf(av, bv.y, acc[j][1]);
                acc[j][2] = fmaf(av, bv.z, acc[j][2]);
                acc[j][3] = fmaf(av, bv.w, acc[j][3]);
            }
        }
        __syncthreads();
    }
    float4 bb4 = *(const float4*)&bias[n0 + tn * 4];
    #pragma unroll
    for (int j = 0; j < 4; j++) {
        float4 o;
        o.x = acc[j][0] + bb4.x; o.y = acc[j][1] + bb4.y;
        o.z = acc[j][2] + bb4.z; o.w = acc[j][3] + bb4.w;
        *(float4*)&g_GX[(size_t)(m0 + tm * 4 + j) * G4 + n0 + tn * 4] = o;
    }
}

// ---------------- K3b: repack GX [b*t][g] -> GXT [t][g][b] ------------------
__global__ void k_repack() {
    __shared__ float tile[32][33];
    int t = blockIdx.x;
    int c0 = blockIdx.y * 32;
    int b0 = blockIdx.z * 32;
    int tx = threadIdx.x & 31, ty = threadIdx.x >> 5;   // 32 x 8
    #pragma unroll
    for (int j = 0; j < 4; j++) {
        int row = ty + j * 8;        // b offset
        tile[row][tx] = g_GX[((size_t)(b0 + row) * NT + t) * G4 + c0 + tx];
    }
    __syncthreads();
    #pragma unroll
    for (int j = 0; j < 4; j++) {
        int row = ty + j * 8;        // c offset
        g_GXT[((size_t)t * G4 + c0 + row) * 64 + b0 + tx] = tile[tx][row];
    }
}

// ------------------------------ K4: LSTM recurrence -------------------------
// 128 persistent blocks x 256 threads. Block bk owns h-dims {2bk,2bk+1} -> 8 gate cols.
// Thread (p = tid&15 : 4 batches, q = (tid>>4)&3 : 2 cols, u = tid>>6 : k-quarter).
// smem: hs[256*64] | Ws2[256*16] (pair-duplicated W) | gred[4*8*64] | csm[128]
#define LSTM_SMEM ((NH * 64 + NH * 16 + 4 * 8 * 64 + 128) * 4)

__global__ void __launch_bounds__(256, 1) k_lstm(const float* __restrict__ Whh) {
    extern __shared__ float sm[];
    float* hs   = sm;                       // 16384 f
    float* Ws2  = hs + NH * 64;             // 4096 f
    float* gred = Ws2 + NH * 16;            // 2048 f
    float* csm  = gred + 4 * 8 * 64;        // 128 f

    int bk = blockIdx.x;
    int tid = threadIdx.x;
    int p = tid & 15, q = (tid >> 4) & 3, u = tid >> 6;

    // one-time: duplicated W slice. col c: g = c&3, hi = c>>2
    for (int idx = tid; idx < NH * 8; idx += 256) {
        int k = idx >> 3, c = idx & 7;
        float w = Whh[(size_t)k * G4 + (c & 3) * NH + 2 * bk + (c >> 2)];
        Ws2[idx * 2] = w;
        Ws2[idx * 2 + 1] = w;
    }
    if (tid < 128) csm[tid] = 1.0f;
    __syncthreads();

    int bbg = tid & 63, hig = (tid >> 6) & 1;   // gate-phase mapping (tid<128)

    for (int t = 0; t < NT; t++) {
        const float* hin = g_h[t & 1];
        float* hout = g_h[(t + 1) & 1];

        // prefetch gx (coalesced from GXT[t][col][b])
        float pg[4];
        if (tid < 128) {
            const float* gp = g_GXT + ((size_t)t * G4 + 2 * bk + hig) * 64 + bbg;
            #pragma unroll
            for (int g = 0; g < 4; g++) pg[g] = __ldcs(gp + (size_t)g * NH * 64);
        }

        // stage first half of h (k 0..127)
        float4 r1[8];
        #pragma unroll
        for (int j = 0; j < 8; j++)
            r1[j] = __ldcg((const float4*)(hin + tid * 4 + j * 1024));
        #pragma unroll
        for (int j = 0; j < 8; j++)
            *(float4*)(hs + tid * 4 + j * 1024) = r1[j];
        __syncthreads();

        // issue loads for second half (overlap with phase A)
        float4 r2[8];
        #pragma unroll
        for (int j = 0; j < 8; j++)
            r2[j] = __ldcg((const float4*)(hin + 8192 + tid * 4 + j * 1024));

        unsigned long long a0 = 0ull, a1 = 0ull, a2 = 0ull, a3 = 0ull;
        {   // phase A: k in [u*32, u*32+32)
            const float* hp = hs + (u * 32) * 64 + 4 * p;
            const float* wp = Ws2 + (u * 32) * 16 + 4 * q;
            #pragma unroll
            for (int k = 0; k < 32; k++) {
                ulonglong2 hv = *(const ulonglong2*)hp;
                ulonglong2 wv = *(const ulonglong2*)wp;
                ffma2(a0, hv.x, wv.x);
                ffma2(a1, hv.y, wv.x);
                ffma2(a2, hv.x, wv.y);
                ffma2(a3, hv.y, wv.y);
                hp += 64; wp += 16;
            }
        }
        #pragma unroll
        for (int j = 0; j < 8; j++)
            *(float4*)(hs + 8192 + tid * 4 + j * 1024) = r2[j];
        __syncthreads();
        {   // phase B: k in [128 + u*32, ...)
            const float* hp = hs + (128 + u * 32) * 64 + 4 * p;
            const float* wp = Ws2 + (128 + u * 32) * 16 + 4 * q;
            #pragma unroll
            for (int k = 0; k < 32; k++) {
                ulonglong2 hv = *(const ulonglong2*)hp;
                ulonglong2 wv = *(const ulonglong2*)wp;
                ffma2(a0, hv.x, wv.x);
                ffma2(a1, hv.y, wv.x);
                ffma2(a2, hv.x, wv.y);
                ffma2(a3, hv.y, wv.y);
                hp += 64; wp += 16;
            }
        }
        // partials: gred[u][col][bb]
        {
            float* gr = gred + ((u * 8 + 2 * q) * 64 + 4 * p);
            ulonglong2 v01; v01.x = a0; v01.y = a1;
            ulonglong2 v23; v23.x = a2; v23.y = a3;
            *(ulonglong2*)gr = v01;
            *(ulonglong2*)(gr + 64) = v23;
        }
        __syncthreads();

        if (tid < 128) {
            float gv[4];
            #pragma unroll
            for (int g = 0; g < 4; g++) {
                int c = hig * 4 + g;
                float s = gred[(0 * 8 + c) * 64 + bbg] + gred[(1 * 8 + c) * 64 + bbg]
                        + gred[(2 * 8 + c) * 64 + bbg] + gred[(3 * 8 + c) * 64 + bbg];
                gv[g] = s + pg[g];
            }
            float i_t = sigmoidf_(gv[0]);
            float f_t = sigmoidf_(gv[1]);
            float g_t = tanhf(gv[2]);
            float o_t = sigmoidf_(gv[3]);
            float cc = f_t * csm[tid] + i_t * g_t;
            csm[tid] = cc;
            __stcg(&hout[(2 * bk + hig) * 64 + bbg], o_t * tanhf(cc));
        }
        __syncthreads();

        // grid barrier
        if (tid == 0) {
            __threadfence();
            atomicAdd(&g_bar, 1u);
            unsigned target = 128u * (unsigned)(t + 1);
            while (*(volatile unsigned*)&g_bar < target) { }
        }
        __syncthreads();
    }
}

// ------------------------------ K5: head + softmax --------------------------
__global__ void k_head(const float* __restrict__ Wfc, const float* __restrict__ bfc,
                       float* __restrict__ out) {
    int b = blockIdx.x;
    int lane = threadIdx.x;    // 32
    __shared__ float hsm[NH];
    for (int k = lane; k < NH; k += 32) hsm[k] = g_h[0][k * 64 + b];
    __syncwarp();
    float l = -1e30f;
    if (lane < NC) {
        float acc = bfc[lane];
        #pragma unroll 8
        for (int k = 0; k < NH; k++) acc = fmaf(hsm[k], Wfc[lane * NH + k], acc);
        l = acc;
    }
    float m = l;
    for (int o = 16; o; o >>= 1) m = fmaxf(m, __shfl_xor_sync(~0u, m, o));
    float e = (lane < NC) ? __expf(l - m) : 0.0f;
    float s = e;
    for (int o = 16; o; o >>= 1) s += __shfl_xor_sync(~0u, s, o);
    if (lane < NC) out[b * NC + lane] = e / s;
}

// ------------------------------ launch --------------------------------------
extern "C" void kernel_launch(void* const* d_in, const int* in_sizes, int n_in,
                              void* d_out, int out_size) {
    const float* x    = (const float*)d_in[0];
    const float* W_ih = (const float*)d_in[1];
    const float* W_hh = (const float*)d_in[2];
    const float* b    = (const float*)d_in[3];
    const float* W1   = (const float*)d_in[4];
    const float* b1   = (const float*)d_in[5];
    const float* W2   = (const float*)d_in[6];
    const float* b2   = (const float*)d_in[7];
    const float* Wfc  = (const float*)d_in[8];
    const float* bfc  = (const float*)d_in[9];
    float* out = (float*)d_out;

    cudaFuncSetAttribute(k_lstm, cudaFuncAttributeMaxDynamicSharedMemorySize, LSTM_SMEM);

    k_init<<<64, 256>>>();
    k_scores<<<4096, 256>>>(x, W1, b1, W2, b2);
    k_maxexp<<<NB * NR, 128>>>();
    k_chunksum<<<NB * 8, 256>>>(x);
    k_prefix2<<<NB * 8, 512>>>(x);
    {
        dim3 grid(512, 16);
        k_gemm<<<grid, 256>>>(W_ih, b);
    }
    {
        dim3 grid(NT, 32, 2);
        k_repack<<<grid, 256>>>();
    }
    k_lstm<<<128, 256, LSTM_SMEM>>>(W_hh);
    k_head<<<NB, 32>>>(Wfc, bfc, out);
}